// round 10
// baseline (speedup 1.0000x reference)
#include <cuda_runtime.h>
#include <cuda_bf16.h>
#include <math.h>

#define B_ 8
#define C_ 64
#define H_ 128
#define W_ 128
#define HS 256
#define WS 256

// ---------------------------------------------------------------------------
// Single fused kernel, minimal-register design.
// Block = 256 thr = 8 warps, covers ONE low-res row (b, y).
//   Phase 1: warps 0-5 compute channel-mean of rows y-1,y,y+1 (2 half-channel
//            sums per row) into smem.
//   Phase 2: thread = (pixel X, sub-row ir): 18 weights in registers.
//   Phase 3: channel loop: 3 scalar loads + shuffles + 18 FFMA + STG.64.
// Forced to <=64 regs -> 4 CTAs/SM = 32 resident warps.
// ---------------------------------------------------------------------------
__global__ void __launch_bounds__(256, 4) carafe_full_kernel(
    const float* __restrict__ x,
    const float* __restrict__ w_off,
    const float* __restrict__ b_off,
    float* __restrict__ out)
{
    __shared__ float smA[3][128];      // channel half 0 sums
    __shared__ float smB[3][128];      // channel half 1 sums
    __shared__ float sc0[2][2][9];     // collapsed 5x5 conv coeffs, out-ch 0
    __shared__ float sc1[2][2][9];     // out-ch 1
    __shared__ float sbias[2];

    if (threadIdx.x < 4) {
        int ir = threadIdx.x >> 1, j = threadIdx.x & 1;
        float a0[9], a1[9];
#pragma unroll
        for (int k = 0; k < 9; k++) { a0[k] = 0.f; a1[k] = 0.f; }
#pragma unroll
        for (int pp = 0; pp < 5; pp++)
#pragma unroll
            for (int qq = 0; qq < 5; qq++) {
                int k = (((ir + pp - 2) >> 1) + 1) * 3 + (((j + qq - 2) >> 1) + 1);
                a0[k] += w_off[pp * 5 + qq];
                a1[k] += w_off[25 + pp * 5 + qq];
            }
#pragma unroll
        for (int k = 0; k < 9; k++) { sc0[ir][j][k] = a0[k]; sc1[ir][j][k] = a1[k]; }
    }
    if (threadIdx.x < 2) sbias[threadIdx.x] = b_off[threadIdx.x];

    int b = blockIdx.x >> 7;           // 1024 blocks: (b, y)
    int y = blockIdx.x & 127;
    int warp = threadIdx.x >> 5;
    int lane = threadIdx.x & 31;

    // ---- Phase 1: mean rows y-1..y+1 (warp = (row, channel-half)) ----
    if (warp < 6) {
        int r = warp >> 1, h = warp & 1;
        int yy = y - 1 + r;
        float4 s0 = make_float4(0.f, 0.f, 0.f, 0.f);
        float4 s1 = make_float4(0.f, 0.f, 0.f, 0.f);
        if (yy >= 0 && yy < H_) {
            const float4* base =
                (const float4*)(x + ((size_t)b << 20) + ((size_t)(h * 32) << 14)
                                + yy * W_) + lane;
#pragma unroll
            for (int c = 0; c < 32; c += 2) {
                float4 v0 = base[(size_t)c << 12];
                float4 v1 = base[(size_t)(c + 1) << 12];
                s0.x += v0.x; s0.y += v0.y; s0.z += v0.z; s0.w += v0.w;
                s1.x += v1.x; s1.y += v1.y; s1.z += v1.z; s1.w += v1.w;
            }
        }
        float4 t = make_float4(s0.x + s1.x, s0.y + s1.y, s0.z + s1.z, s0.w + s1.w);
        if (h == 0) *(float4*)&smA[r][4 * lane] = t;
        else        *(float4*)&smB[r][4 * lane] = t;
    }
    __syncthreads();

    // ---- Phase 2: per-thread weights (1 pixel, 1 sub-row, 2 sub-cols) ----
    int seg = warp & 3;                // pixel segment
    int ir  = (warp >> 2) & 1;         // hi-res sub-row
    int X   = seg * 32 + lane;         // low-res col

    float w18[18];
    {
        float m0[9];
#pragma unroll
        for (int rr = 0; rr < 3; rr++)
#pragma unroll
            for (int cc = 0; cc < 3; cc++) {
                int Xc = X - 1 + cc;
                m0[rr * 3 + cc] = (Xc >= 0 && Xc < W_)
                    ? (smA[rr][Xc] + smB[rr][Xc]) * (1.0f / 64.0f) : 0.f;
            }
        float g9[9];
        float mc = m0[4];
#pragma unroll
        for (int k = 0; k < 9; k++) {
            float d = m0[k] - mc;
            g9[k] = __fdividef(1.0f, d * d + 1.0f);
        }
#pragma unroll
        for (int j = 0; j < 2; j++) {
            float o0 = 0.f, o1 = 0.f;
#pragma unroll
            for (int k = 0; k < 9; k++) {
                o0 = fmaf(m0[k], sc0[ir][j][k], o0);
                o1 = fmaf(m0[k], sc1[ir][j][k], o1);
            }
            float s0 = (ir ? 0.25f : -0.25f) + 0.25f * tanhf(o0 + sbias[0]);
            float s1 = (j  ? 0.25f : -0.25f) + 0.25f * tanhf(o1 + sbias[1]);
            float sum = 0.f;
            float lv[9];
#pragma unroll
            for (int k = 0; k < 9; k++) {
                float d0 = s0 - (float)(k / 3 - 1);
                float d1 = s1 - (float)(k % 3 - 1);
                float ker = __fdividef(1.0f, d0 * d0 + d1 * d1 + 0.5f);
                lv[k] = __expf(g9[k] * ker);   // arg in (0,2]: no max-sub
                sum += lv[k];
            }
            float sinv = __fdividef(1.0f, sum);
#pragma unroll
            for (int k = 0; k < 9; k++) w18[j * 9 + k] = lv[k] * sinv;
        }
    }

    // ---- Phase 3: CARAFE channel loop ----
    bool hasN = (y > 0), hasS = (y < H_ - 1);
    bool l0 = (lane == 0), l31 = (lane == 31);
    const float* px = x + ((size_t)b << 20) + y * W_ + X;
    float* ob = out + (size_t)(b * C_) * (HS * WS)
                    + (size_t)(2 * y + ir) * WS + 2 * X;
    const unsigned msk = 0xffffffffu;

#pragma unroll 1
    for (int c = 0; c < C_; c++) {
        float v0 = hasN ? __ldg(px - W_) : 0.f;
        float v1 = __ldg(px);
        float v2 = hasS ? __ldg(px + W_) : 0.f;

        float lf0 = __shfl_up_sync(msk, v0, 1);
        float lf1 = __shfl_up_sync(msk, v1, 1);
        float lf2 = __shfl_up_sync(msk, v2, 1);
        float rt0 = __shfl_down_sync(msk, v0, 1);
        float rt1 = __shfl_down_sync(msk, v1, 1);
        float rt2 = __shfl_down_sync(msk, v2, 1);

        if (l0) {                       // seam / image-left edge
            if (seg > 0) {
                lf0 = hasN ? __ldg(px - W_ - 1) : 0.f;
                lf1 = __ldg(px - 1);
                lf2 = hasS ? __ldg(px + W_ - 1) : 0.f;
            } else { lf0 = 0.f; lf1 = 0.f; lf2 = 0.f; }
        }
        if (l31) {                      // seam / image-right edge
            if (seg < 3) {
                rt0 = hasN ? __ldg(px - W_ + 1) : 0.f;
                rt1 = __ldg(px + 1);
                rt2 = hasS ? __ldg(px + W_ + 1) : 0.f;
            } else { rt0 = 0.f; rt1 = 0.f; rt2 = 0.f; }
        }

        float a0 = 0.f, a1 = 0.f;
        a0 = fmaf(w18[0], lf0, a0);  a1 = fmaf(w18[9],  lf0, a1);
        a0 = fmaf(w18[1], v0,  a0);  a1 = fmaf(w18[10], v0,  a1);
        a0 = fmaf(w18[2], rt0, a0);  a1 = fmaf(w18[11], rt0, a1);
        a0 = fmaf(w18[3], lf1, a0);  a1 = fmaf(w18[12], lf1, a1);
        a0 = fmaf(w18[4], v1,  a0);  a1 = fmaf(w18[13], v1,  a1);
        a0 = fmaf(w18[5], rt1, a0);  a1 = fmaf(w18[14], rt1, a1);
        a0 = fmaf(w18[6], lf2, a0);  a1 = fmaf(w18[15], lf2, a1);
        a0 = fmaf(w18[7], v2,  a0);  a1 = fmaf(w18[16], v2,  a1);
        a0 = fmaf(w18[8], rt2, a0);  a1 = fmaf(w18[17], rt2, a1);

        __stcs((float2*)ob, make_float2(a0, a1));

        px += 16384;                   // next channel
        ob += (size_t)HS * WS;
    }
}

extern "C" void kernel_launch(void* const* d_in, const int* in_sizes, int n_in,
                              void* d_out, int out_size)
{
    const float* x     = (const float*)d_in[0];   // [8,64,128,128]
    const float* w_off = (const float*)d_in[1];   // [2,1,5,5]
    const float* b_off = (const float*)d_in[2];   // [2]
    float* out = (float*)d_out;                   // [8,64,256,256]

    carafe_full_kernel<<<B_ * H_, 256>>>(x, w_off, b_off, out);
}